// round 9
// baseline (speedup 1.0000x reference)
#include <cuda_runtime.h>
#include <cuda_bf16.h>
#include <cstdint>

// Problem constants
#define BSZ    4096
#define DD     256
#define MARGIN 0.5f

#define TILE    128              // 128x128 sim tiles
#define NTILES  (BSZ / TILE)     // 32

// Dynamic smem: A tile (64KB) then B tile (64KB), both [128 rows][512B] XOR-swizzled
#define SMEM_A_OFF 0
#define SMEM_B_OFF 65536
#define SMEM_BYTES 131072

// Device scratch (no cudaMalloc allowed)
__device__ __align__(16) __nv_bfloat16 g_fbf[BSZ * DD];   // bf16 copy of ftr
__device__ unsigned long long g_min[BSZ];                 // bf16 global min (packed)
__device__ unsigned long long g_tilemin[BSZ * NTILES];    // bf16 per-tile min (packed)
__device__ int                g_label[BSZ];
__device__ int                g_negidx[BSZ];              // exact argmin column
__device__ float              g_loss[BSZ];

// Monotone float<->uint key (smaller float => smaller key)
__device__ __forceinline__ unsigned int fkey(float x) {
    unsigned int u = __float_as_uint(x);
    return (u & 0x80000000u) ? ~u : (u | 0x80000000u);
}
__device__ __forceinline__ float unkey(unsigned int k) {
    unsigned int u = (k & 0x80000000u) ? (k & 0x7FFFFFFFu) : ~k;
    return __uint_as_float(u);
}
__device__ __forceinline__ uint32_t smem_u32(const void* p) {
    uint32_t a;
    asm("{ .reg .u64 t; cvta.to.shared.u64 t, %1; cvt.u32.u64 %0, t; }" : "=r"(a) : "l"(p));
    return a;
}
#define LDSM_X4(r, addr)                                                     \
    asm volatile("ldmatrix.sync.aligned.m8n8.x4.shared.b16 {%0,%1,%2,%3}, [%4];" \
        : "=r"((r)[0]), "=r"((r)[1]), "=r"((r)[2]), "=r"((r)[3]) : "r"(addr))

__device__ __forceinline__ void mma_bf16(float* c, const uint32_t* a,
                                         uint32_t b0, uint32_t b1) {
    asm volatile(
        "mma.sync.aligned.m16n8k16.row.col.f32.bf16.bf16.f32 "
        "{%0,%1,%2,%3}, {%4,%5,%6,%7}, {%8,%9}, {%0,%1,%2,%3};"
        : "+f"(c[0]), "+f"(c[1]), "+f"(c[2]), "+f"(c[3])
        : "r"(a[0]), "r"(a[1]), "r"(a[2]), "r"(a[3]), "r"(b0), "r"(b1));
}

// ---------------------------------------------------------------------------
// Prologue: label dtype sniff + normalize, init mins, convert ftr -> bf16.
// ---------------------------------------------------------------------------
__global__ void prologue_kernel(const float* __restrict__ ftr,
                                const int* __restrict__ lab32) {
    __shared__ int is64;
    if (threadIdx.x == 0) {
        int odd_or = 0;
        #pragma unroll
        for (int i = 0; i < 32; i++) odd_or |= lab32[2 * i + 1];
        is64 = (odd_or == 0) ? 1 : 0;
    }
    __syncthreads();
    const int i = blockIdx.x * blockDim.x + threadIdx.x;   // 0 .. 524287
    const float2 f2 = ((const float2*)ftr)[i];
    __nv_bfloat162 b2;
    b2.x = __float2bfloat16(f2.x);
    b2.y = __float2bfloat16(f2.y);
    ((__nv_bfloat162*)g_fbf)[i] = b2;
    if (i < BSZ) {
        g_label[i] = is64 ? lab32[2 * i] : lab32[i];
        g_min[i]   = 0xFFFFFFFFFFFFFFFFull;
    }
    if (i < BSZ * NTILES) g_tilemin[i] = 0xFFFFFFFFFFFFFFFFull;
}

// ---------------------------------------------------------------------------
// bf16 HMMA sim tile + per-row masked argmin (bf16 precision).
// CTA: 256 threads = 8 warps (4 M x 2 N), warp tile 32x64, K=256 resident.
// SMEM layout per operand: row r (0..127) at r*512 bytes; 16B chunk c (0..31)
// at ((c ^ (r & 7)) * 16)  -> conflict-free ldmatrix + conflict-free stores.
// ---------------------------------------------------------------------------
__global__ __launch_bounds__(256, 1)
void sim_mma_kernel() {
    extern __shared__ __align__(16) unsigned char dsm[];
    __shared__ int slab[TILE];
    __shared__ unsigned long long rowMin[TILE];

    const int tid  = threadIdx.x;
    const int wid  = tid >> 5;
    const int lane = tid & 31;
    const int row0 = blockIdx.y * TILE;
    const int col0 = blockIdx.x * TILE;

    if (tid < TILE) {
        slab[tid]   = g_label[row0 + tid];
        rowMin[tid] = 0xFFFFFFFFFFFFFFFFull;
    }

    // ---- load A and B tiles (bf16, swizzled) ----
    #pragma unroll
    for (int it = 0; it < 16; it++) {
        const int idx = tid + it * 256;        // 0..4095 16B-chunks
        const int r   = idx >> 5;
        const int c16 = idx & 31;
        const uint4 va = *(const uint4*)(g_fbf + (size_t)(row0 + r) * DD + c16 * 8);
        const uint4 vb = *(const uint4*)(g_fbf + (size_t)(col0 + r) * DD + c16 * 8);
        const uint32_t off = (uint32_t)(r * 512 + ((c16 ^ (r & 7)) << 4));
        *(uint4*)(dsm + SMEM_A_OFF + off) = va;
        *(uint4*)(dsm + SMEM_B_OFF + off) = vb;
    }
    __syncthreads();

    const uint32_t sA = smem_u32(dsm) + SMEM_A_OFF;
    const uint32_t sB = smem_u32(dsm) + SMEM_B_OFF;

    const int wm = (wid >> 1) * 32;            // warp M offset in tile
    const int wn = (wid & 1) * 64;             // warp N offset in tile

    // ldmatrix lane-address rows (within tile)
    // A x4 (m16 x k16): lanes 0-7 rows m0-7 kLo | 8-15 m8-15 kLo | 16-23 m0-7 kHi | 24-31 m8-15 kHi
    int rowA[2];
    #pragma unroll
    for (int mi = 0; mi < 2; mi++)
        rowA[mi] = wm + mi * 16 + ((lane >> 3) & 1) * 8 + (lane & 7);
    const int cbitA = lane >> 4;
    // B x4 (n16 x k16): lanes 0-7 n0-7 kLo | 8-15 n0-7 kHi | 16-23 n8-15 kLo | 24-31 n8-15 kHi
    int rowB[4];
    #pragma unroll
    for (int nb = 0; nb < 4; nb++)
        rowB[nb] = wn + nb * 16 + ((lane >> 4) & 1) * 8 + (lane & 7);
    const int cbitB = (lane >> 3) & 1;

    float acc[2][8][4];
    #pragma unroll
    for (int mi = 0; mi < 2; mi++)
        #pragma unroll
        for (int nj = 0; nj < 8; nj++)
            #pragma unroll
            for (int q = 0; q < 4; q++) acc[mi][nj][q] = 0.0f;

    // ---- main loop: 16 k-steps of k16 ----
    #pragma unroll
    for (int ks = 0; ks < 16; ks++) {
        uint32_t a[2][4];
        #pragma unroll
        for (int mi = 0; mi < 2; mi++) {
            const int r = rowA[mi];
            const uint32_t ch = (uint32_t)(2 * ks + cbitA);
            LDSM_X4(a[mi], sA + r * 512 + ((ch ^ (r & 7)) << 4));
        }
        uint32_t b[4][4];
        #pragma unroll
        for (int nb = 0; nb < 4; nb++) {
            const int r = rowB[nb];
            const uint32_t ch = (uint32_t)(2 * ks + cbitB);
            LDSM_X4(b[nb], sB + r * 512 + ((ch ^ (r & 7)) << 4));
        }
        #pragma unroll
        for (int mi = 0; mi < 2; mi++)
            #pragma unroll
            for (int nj = 0; nj < 8; nj++)
                mma_bf16(acc[mi][nj], a[mi],
                         b[nj >> 1][(nj & 1) * 2], b[nj >> 1][(nj & 1) * 2 + 1]);
    }

    // ---- epilogue: masked argmin directly on C fragments ----
    // C frag layout (m16n8): c0,c1 -> row g=lane>>2, cols (lane&3)*2 + {0,1};
    //                        c2,c3 -> row g+8, same cols.
    #pragma unroll
    for (int mi = 0; mi < 2; mi++) {
        #pragma unroll
        for (int rh = 0; rh < 2; rh++) {
            const int lrow = wm + mi * 16 + rh * 8 + (lane >> 2);
            const int lab  = slab[lrow];
            unsigned long long best = 0xFFFFFFFFFFFFFFFFull;
            #pragma unroll
            for (int nj = 0; nj < 8; nj++) {
                const int colA = col0 + wn + nj * 8 + (lane & 3) * 2;
                const float v0 = acc[mi][nj][2 * rh + 0];
                const float v1 = acc[mi][nj][2 * rh + 1];
                if (colA != lab) {
                    unsigned long long p =
                        ((unsigned long long)fkey(v0) << 32) | (unsigned)colA;
                    best = (p < best) ? p : best;
                }
                if (colA + 1 != lab) {
                    unsigned long long p =
                        ((unsigned long long)fkey(v1) << 32) | (unsigned)(colA + 1);
                    best = (p < best) ? p : best;
                }
            }
            // reduce across the 4 lanes sharing this row (same lane>>2)
            #pragma unroll
            for (int o = 1; o < 4; o <<= 1) {
                unsigned long long q = __shfl_xor_sync(0xFFFFFFFFu, best, o);
                best = (q < best) ? q : best;
            }
            if ((lane & 3) == 0) atomicMin(&rowMin[lrow], best);
        }
    }
    __syncthreads();

    if (tid < TILE) {
        const unsigned long long b = rowMin[tid];
        g_tilemin[(size_t)(row0 + tid) * NTILES + blockIdx.x] = b;
        atomicMin(&g_min[row0 + tid], b);
    }
}

// ---------------------------------------------------------------------------
// Exact refinement: recompute fp32 dots for tiles within the bf16 error bound
// of the row's bf16 min; exact masked argmin (lowest-index tie-break).
// One block (128 threads) per row.
// ---------------------------------------------------------------------------
__global__ __launch_bounds__(128)
void refine_kernel(const float* __restrict__ ftr) {
    __shared__ float x[DD];
    __shared__ unsigned long long wbest[4];
    const int r    = blockIdx.x;
    const int tid  = threadIdx.x;
    const int w    = tid >> 5;
    const int lane = tid & 31;

    x[tid]       = ftr[(size_t)r * DD + tid];
    x[tid + 128] = ftr[(size_t)r * DD + tid + 128];
    __syncthreads();

    const float m0     = unkey((unsigned)(g_min[r] >> 32));
    const float thresh = m0 + 4.0f;        // >= 2x hard bf16 dot-error bound
    const int   lab    = g_label[r];

    unsigned long long best = 0xFFFFFFFFFFFFFFFFull;
    for (int t = 0; t < NTILES; t++) {
        const float tv = unkey((unsigned)(g_tilemin[(size_t)r * NTILES + t] >> 32));
        if (tv > thresh) continue;
        const int cb = t * TILE + w * 32;
        for (int j = 0; j < 32; j++) {
            const int col = cb + j;
            const float* fv = ftr + (size_t)col * DD;
            float d = 0.0f;
            #pragma unroll
            for (int m = 0; m < DD / 32; m++)
                d = fmaf(x[lane + 32 * m], fv[lane + 32 * m], d);
            #pragma unroll
            for (int o = 16; o > 0; o >>= 1)
                d += __shfl_down_sync(0xFFFFFFFFu, d, o);
            if (lane == 0 && col != lab) {
                unsigned long long p = ((unsigned long long)fkey(d) << 32) | (unsigned)col;
                best = (p < best) ? p : best;
            }
        }
    }
    if (lane == 0) wbest[w] = best;
    __syncthreads();
    if (tid == 0) {
        unsigned long long b = wbest[0];
        b = (wbest[1] < b) ? wbest[1] : b;
        b = (wbest[2] < b) ? wbest[2] : b;
        b = (wbest[3] < b) ? wbest[3] : b;
        g_negidx[r] = (int)(b & 0xFFFFFFFFull);
    }
}

// ---------------------------------------------------------------------------
// Per-row loss: one warp per row (exact fp32).
// ---------------------------------------------------------------------------
__global__ __launch_bounds__(256)
void loss_kernel(const float* __restrict__ ftr,
                 const float* __restrict__ prototypes) {
    const int warp = (blockIdx.x * blockDim.x + threadIdx.x) >> 5;
    const int lane = threadIdx.x & 31;
    if (warp >= BSZ) return;
    const int r   = warp;
    const int lab = g_label[r];
    const int ni  = g_negidx[r];

    const float* xp = ftr + (size_t)r * DD;
    const float* yp = prototypes + (size_t)lab * DD;
    const float* np = ftr + (size_t)ni * DD;

    float pd = 0.0f, nd = 0.0f;
    #pragma unroll
    for (int t = 0; t < DD / 32; t++) {
        const int c = lane + t * 32;
        const float xv = xp[c];
        const float dy = xv - yp[c];
        const float dn = xv - np[c];
        pd = fmaf(dy, dy, pd);
        nd = fmaf(dn, dn, nd);
    }
    #pragma unroll
    for (int o = 16; o > 0; o >>= 1) {
        pd += __shfl_down_sync(0xFFFFFFFFu, pd, o);
        nd += __shfl_down_sync(0xFFFFFFFFu, nd, o);
    }
    if (lane == 0) g_loss[r] = fmaxf(pd - nd + MARGIN, 0.0f);
}

// ---------------------------------------------------------------------------
// Deterministic mean reduction (shuffle tree).
// ---------------------------------------------------------------------------
__global__ void reduce_kernel(float* __restrict__ out) {
    __shared__ float s[32];
    const int t = threadIdx.x;   // 1024
    float v = g_loss[t] + g_loss[t + 1024] + g_loss[t + 2048] + g_loss[t + 3072];
    #pragma unroll
    for (int o = 16; o > 0; o >>= 1) v += __shfl_down_sync(0xFFFFFFFFu, v, o);
    if ((t & 31) == 0) s[t >> 5] = v;
    __syncthreads();
    if (t < 32) {
        float w = s[t];
        #pragma unroll
        for (int o = 16; o > 0; o >>= 1) w += __shfl_down_sync(0xFFFFFFFFu, w, o);
        if (t == 0) out[0] = w / (float)BSZ;
    }
}

extern "C" void kernel_launch(void* const* d_in, const int* in_sizes, int n_in,
                              void* d_out, int out_size) {
    const float* ftr        = (const float*)d_in[0];
    // d_in[1] = teachor_ftr : unused by the reference computation
    const float* prototypes = (const float*)d_in[2];
    const int*   label_raw  = (const int*)d_in[3];   // int32 or int64 — sniffed on device
    float*       out        = (float*)d_out;

    cudaFuncSetAttribute(sim_mma_kernel,
                         cudaFuncAttributeMaxDynamicSharedMemorySize, SMEM_BYTES);

    prologue_kernel<<<(BSZ * DD / 2) / 256, 256>>>(ftr, label_raw);

    dim3 grid(NTILES, NTILES);   // 32 x 32 = 1024 tiles
    sim_mma_kernel<<<grid, 256, SMEM_BYTES>>>();

    refine_kernel<<<BSZ, 128>>>(ftr);

    loss_kernel<<<(BSZ * 32) / 256, 256>>>(ftr, prototypes);

    reduce_kernel<<<1, 1024>>>(out);
}

// round 10
// speedup vs baseline: 1.9724x; 1.9724x over previous
#include <cuda_runtime.h>

// Problem constants
#define BSZ    4096
#define DD     256
#define MARGIN 0.5f

// GEMM tiling
#define BM 128
#define BN 128
#define BK 16
#define NT (DD / BK)       // 16 k-tiles
#define PAD 4              // smem row padding
#define NTILES (BSZ / BM)  // 32 tile-blocks per dim
#define NBLK (NTILES * (NTILES + 1) / 2)   // 528 upper-triangular tiles

// Scratch (no cudaMalloc allowed)
__device__ unsigned long long g_min[BSZ];   // packed (fkey(simval)<<32 | col)
__device__ float              g_loss[BSZ];
__device__ int                g_label[BSZ];

// Monotone increasing float -> uint mapping (smaller float => smaller key)
__device__ __forceinline__ unsigned int fkey(float x) {
    unsigned int u = __float_as_uint(x);
    return (u & 0x80000000u) ? ~u : (u | 0x80000000u);
}

// ---------------------------------------------------------------------------
// Prologue: label dtype sniff (int32 vs little-endian int64) + init g_min.
// ---------------------------------------------------------------------------
__global__ void prologue_kernel(const int* __restrict__ lab32) {
    __shared__ int is64;
    if (threadIdx.x == 0) {
        int odd_or = 0;
        #pragma unroll
        for (int i = 0; i < 32; i++) odd_or |= lab32[2 * i + 1];
        is64 = (odd_or == 0) ? 1 : 0;
    }
    __syncthreads();
    const int i = blockIdx.x * blockDim.x + threadIdx.x;
    if (i < BSZ) {
        g_label[i] = is64 ? lab32[2 * i] : lab32[i];
        g_min[i]   = 0xFFFFFFFFFFFFFFFFull;
    }
}

// ---------------------------------------------------------------------------
// Fused sim tile + bidirectional masked argmin over the upper triangle.
// Tile (bi,bj), bi<=bj: S[x][y] = dot(ftr[bi*128+x], ftr[bj*128+y]).
//   row-direction: rows bi-block, candidate cols bj-block
//   col-direction (bi!=bj): rows bj-block, candidate cols bi-block (transposed)
// Block: 256 threads, 128x128 tile, 8x8 per thread (R6-proven GEMM core).
// ---------------------------------------------------------------------------
__global__ __launch_bounds__(256)
void sim_argmin_kernel(const float* __restrict__ ftr) {
    __shared__ __align__(16) float As[2][BK][BM + PAD];
    __shared__ __align__(16) float Bs[2][BK][BN + PAD];
    __shared__ unsigned long long rowMin[BM];
    __shared__ unsigned long long colMin[BN];
    __shared__ int slabR[BM];    // labels of row-block rows
    __shared__ int slabC[BN];    // labels of col-block rows

    // triangular decode: blockIdx.x -> (bi, bj), bi <= bj
    int t = blockIdx.x, bi = 0;
    #pragma unroll 1
    for (;;) {
        const int len = NTILES - bi;
        if (t < len) break;
        t -= len;
        bi++;
    }
    const int bj   = bi + t;
    const int row0 = bi * BM;
    const int col0 = bj * BN;
    const bool offdiag = (bi != bj);

    const int tid = threadIdx.x;
    const int tx  = tid & 15;
    const int ty  = tid >> 4;

    if (tid < BM) {
        rowMin[tid] = 0xFFFFFFFFFFFFFFFFull;
        colMin[tid] = 0xFFFFFFFFFFFFFFFFull;
        slabR[tid]  = g_label[row0 + tid];
        slabC[tid]  = g_label[col0 + tid];
    }

    float acc[8][8];
    #pragma unroll
    for (int i = 0; i < 8; i++)
        #pragma unroll
        for (int j = 0; j < 8; j++)
            acc[i][j] = 0.0f;

    // ---- preload k-tile 0 ----
    {
        #pragma unroll
        for (int l = 0; l < 2; l++) {
            int f = tid + l * 256;
            int r = f >> 2, kq = f & 3;
            float4 va = *(const float4*)(ftr + (size_t)(row0 + r) * DD + kq * 4);
            float4 vb = *(const float4*)(ftr + (size_t)(col0 + r) * DD + kq * 4);
            As[0][kq * 4 + 0][r] = va.x; As[0][kq * 4 + 1][r] = va.y;
            As[0][kq * 4 + 2][r] = va.z; As[0][kq * 4 + 3][r] = va.w;
            Bs[0][kq * 4 + 0][r] = vb.x; Bs[0][kq * 4 + 1][r] = vb.y;
            Bs[0][kq * 4 + 2][r] = vb.z; Bs[0][kq * 4 + 3][r] = vb.w;
        }
    }
    __syncthreads();

    // ---- main loop over k-tiles, double buffered ----
    for (int kt = 0; kt < NT; kt++) {
        const int cur = kt & 1;
        float4 va[2], vb[2];
        const bool more = (kt + 1) < NT;

        if (more) {
            const int k0 = (kt + 1) * BK;
            #pragma unroll
            for (int l = 0; l < 2; l++) {
                int f = tid + l * 256;
                int r = f >> 2, kq = f & 3;
                va[l] = *(const float4*)(ftr + (size_t)(row0 + r) * DD + k0 + kq * 4);
                vb[l] = *(const float4*)(ftr + (size_t)(col0 + r) * DD + k0 + kq * 4);
            }
        }

        #pragma unroll
        for (int k = 0; k < BK; k++) {
            float a[8], b[8];
            *(float4*)&a[0] = *(const float4*)&As[cur][k][ty * 8 + 0];
            *(float4*)&a[4] = *(const float4*)&As[cur][k][ty * 8 + 4];
            *(float4*)&b[0] = *(const float4*)&Bs[cur][k][tx * 8 + 0];
            *(float4*)&b[4] = *(const float4*)&Bs[cur][k][tx * 8 + 4];
            #pragma unroll
            for (int i = 0; i < 8; i++)
                #pragma unroll
                for (int j = 0; j < 8; j++)
                    acc[i][j] = fmaf(a[i], b[j], acc[i][j]);
        }

        if (more) {
            const int nb = cur ^ 1;
            #pragma unroll
            for (int l = 0; l < 2; l++) {
                int f = tid + l * 256;
                int r = f >> 2, kq = f & 3;
                As[nb][kq * 4 + 0][r] = va[l].x; As[nb][kq * 4 + 1][r] = va[l].y;
                As[nb][kq * 4 + 2][r] = va[l].z; As[nb][kq * 4 + 3][r] = va[l].w;
                Bs[nb][kq * 4 + 0][r] = vb[l].x; Bs[nb][kq * 4 + 1][r] = vb[l].y;
                Bs[nb][kq * 4 + 2][r] = vb[l].z; Bs[nb][kq * 4 + 3][r] = vb[l].w;
            }
        }
        __syncthreads();
    }

    // ---- epilogue: row-direction masked argmin ----
    #pragma unroll
    for (int i = 0; i < 8; i++) {
        const int gi  = ty * 8 + i;
        const int lab = slabR[gi];
        unsigned long long best = 0xFFFFFFFFFFFFFFFFull;
        #pragma unroll
        for (int j = 0; j < 8; j++) {
            const int gj = col0 + tx * 8 + j;
            if (gj != lab) {
                unsigned long long p =
                    ((unsigned long long)fkey(acc[i][j]) << 32) | (unsigned int)gj;
                best = (p < best) ? p : best;
            }
        }
        atomicMin(&rowMin[gi], best);
    }

    // ---- epilogue: col-direction (transposed) masked argmin ----
    if (offdiag) {
        #pragma unroll
        for (int j = 0; j < 8; j++) {
            const int gj  = tx * 8 + j;           // local row in col-block
            const int lab = slabC[gj];
            unsigned long long best = 0xFFFFFFFFFFFFFFFFull;
            #pragma unroll
            for (int i = 0; i < 8; i++) {
                const int gi = row0 + ty * 8 + i; // candidate column (global row idx)
                if (gi != lab) {
                    unsigned long long p =
                        ((unsigned long long)fkey(acc[i][j]) << 32) | (unsigned int)gi;
                    best = (p < best) ? p : best;
                }
            }
            atomicMin(&colMin[gj], best);
        }
    }
    __syncthreads();

    if (tid < BM) {
        atomicMin(&g_min[row0 + tid], rowMin[tid]);
        if (offdiag) atomicMin(&g_min[col0 + tid], colMin[tid]);
    }
}

// ---------------------------------------------------------------------------
// Per-row loss: one warp per row (exact fp32).
// ---------------------------------------------------------------------------
__global__ __launch_bounds__(256)
void loss_kernel(const float* __restrict__ ftr,
                 const float* __restrict__ prototypes) {
    const int warp = (blockIdx.x * blockDim.x + threadIdx.x) >> 5;
    const int lane = threadIdx.x & 31;
    if (warp >= BSZ) return;
    const int r   = warp;
    const int lab = g_label[r];
    const int ni  = (int)(g_min[r] & 0xFFFFFFFFull);

    const float* xp = ftr + (size_t)r * DD;
    const float* yp = prototypes + (size_t)lab * DD;
    const float* np = ftr + (size_t)ni * DD;

    float pd = 0.0f, nd = 0.0f;
    #pragma unroll
    for (int t = 0; t < DD / 32; t++) {
        const int c = lane + t * 32;
        const float xv = xp[c];
        const float dy = xv - yp[c];
        const float dn = xv - np[c];
        pd = fmaf(dy, dy, pd);
        nd = fmaf(dn, dn, nd);
    }
    #pragma unroll
    for (int o = 16; o > 0; o >>= 1) {
        pd += __shfl_down_sync(0xFFFFFFFFu, pd, o);
        nd += __shfl_down_sync(0xFFFFFFFFu, nd, o);
    }
    if (lane == 0) g_loss[r] = fmaxf(pd - nd + MARGIN, 0.0f);
}

// ---------------------------------------------------------------------------
// Deterministic mean reduction (shuffle tree).
// ---------------------------------------------------------------------------
__global__ void reduce_kernel(float* __restrict__ out) {
    __shared__ float s[32];
    const int t = threadIdx.x;   // 1024
    float v = g_loss[t] + g_loss[t + 1024] + g_loss[t + 2048] + g_loss[t + 3072];
    #pragma unroll
    for (int o = 16; o > 0; o >>= 1) v += __shfl_down_sync(0xFFFFFFFFu, v, o);
    if ((t & 31) == 0) s[t >> 5] = v;
    __syncthreads();
    if (t < 32) {
        float w = s[t];
        #pragma unroll
        for (int o = 16; o > 0; o >>= 1) w += __shfl_down_sync(0xFFFFFFFFu, w, o);
        if (t == 0) out[0] = w / (float)BSZ;
    }
}

extern "C" void kernel_launch(void* const* d_in, const int* in_sizes, int n_in,
                              void* d_out, int out_size) {
    const float* ftr        = (const float*)d_in[0];
    // d_in[1] = teachor_ftr : unused by the reference computation
    const float* prototypes = (const float*)d_in[2];
    const int*   label_raw  = (const int*)d_in[3];   // int32 or int64 — sniffed on device
    float*       out        = (float*)d_out;

    prologue_kernel<<<BSZ / 256, 256>>>(label_raw);

    sim_argmin_kernel<<<NBLK, 256>>>(ftr);   // 528 upper-triangular tiles

    loss_kernel<<<(BSZ * 32) / 256, 256>>>(ftr, prototypes);

    reduce_kernel<<<1, 1024>>>(out);
}

// round 11
// speedup vs baseline: 2.2536x; 1.1426x over previous
#include <cuda_runtime.h>
#include <cstdint>

// Problem constants
#define BSZ    4096
#define DD     256
#define MARGIN 0.5f

// GEMM tiling
#define BM 128
#define BN 128
#define BK 16
#define NT (DD / BK)       // 16 k-tiles
#define PAD 4              // smem row padding (132 floats = 33*16B: float4-aligned)
#define NTILES (BSZ / BM)  // 32 tile-blocks per dim
#define NBLK (NTILES * (NTILES + 1) / 2)   // 528 upper-triangular tiles
#define GRID_SIM 296       // 148 SMs x 2 CTAs, work-stealing

// Scratch (no cudaMalloc allowed)
__device__ unsigned long long g_min[BSZ];   // packed (fkey(simval)<<32 | col)
__device__ float              g_loss[BSZ];
__device__ int                g_label[BSZ];
__device__ unsigned int       g_ticket;

// Monotone increasing float -> uint mapping (smaller float => smaller key)
__device__ __forceinline__ unsigned int fkey(float x) {
    unsigned int u = __float_as_uint(x);
    return (u & 0x80000000u) ? ~u : (u | 0x80000000u);
}

// Packed f32x2 helpers (Blackwell FFMA2 path)
#define FMA2(d, a, b) \
    asm("fma.rn.f32x2 %0, %1, %2, %0;" : "+l"(d) : "l"(a), "l"(b))
#define DUP2(d, f) \
    asm("mov.b64 %0, {%1, %1};" : "=l"(d) : "f"(f))
#define UNPK2(lo, hi, d) \
    asm("mov.b64 {%0, %1}, %2;" : "=f"(lo), "=f"(hi) : "l"(d))

// ---------------------------------------------------------------------------
// Prologue: label dtype sniff (int32 vs little-endian int64), init g_min,
// reset the work-stealing ticket (graph-replay safe).
// ---------------------------------------------------------------------------
__global__ void prologue_kernel(const int* __restrict__ lab32) {
    __shared__ int is64;
    if (threadIdx.x == 0) {
        int odd_or = 0;
        #pragma unroll
        for (int i = 0; i < 32; i++) odd_or |= lab32[2 * i + 1];
        is64 = (odd_or == 0) ? 1 : 0;
        if (blockIdx.x == 0) g_ticket = 0u;
    }
    __syncthreads();
    const int i = blockIdx.x * blockDim.x + threadIdx.x;
    if (i < BSZ) {
        g_label[i] = is64 ? lab32[2 * i] : lab32[i];
        g_min[i]   = 0xFFFFFFFFFFFFFFFFull;
    }
}

// ---------------------------------------------------------------------------
// Persistent work-stealing sim tiles + bidirectional masked argmin over the
// upper triangle. Tile (bi,bj), bi<=bj: S[x][y] = dot(ftr[bi*128+x], ftr[bj*128+y]).
// 256 threads, 128x128 tile, 8x8 per thread via packed f32x2 FMA.
// ---------------------------------------------------------------------------
__global__ __launch_bounds__(256, 2)
void sim_argmin_kernel(const float* __restrict__ ftr) {
    __shared__ __align__(16) float As[2][BK][BM + PAD];
    __shared__ __align__(16) float Bs[2][BK][BN + PAD];
    __shared__ unsigned long long rowMin[BM];
    __shared__ unsigned long long colMin[BN];
    __shared__ int slabR[BM];
    __shared__ int slabC[BN];
    __shared__ int s_tile;

    const int tid = threadIdx.x;
    const int tx  = tid & 15;
    const int ty  = tid >> 4;

    for (;;) {
        if (tid == 0) s_tile = (int)atomicAdd(&g_ticket, 1u);
        __syncthreads();
        const int tile = s_tile;
        if (tile >= NBLK) break;

        // triangular decode: tile -> (bi, bj), bi <= bj
        int t = tile, bi = 0;
        #pragma unroll 1
        for (;;) {
            const int len = NTILES - bi;
            if (t < len) break;
            t -= len;
            bi++;
        }
        const int bj   = bi + t;
        const int row0 = bi * BM;
        const int col0 = bj * BN;
        const bool offdiag = (bi != bj);

        if (tid < BM) {
            rowMin[tid] = 0xFFFFFFFFFFFFFFFFull;
            colMin[tid] = 0xFFFFFFFFFFFFFFFFull;
            slabR[tid]  = g_label[row0 + tid];
            slabC[tid]  = g_label[col0 + tid];
        }

        // acc as packed f32x2: 8 rows x 4 col-pairs; 0ull == (+0.0f, +0.0f)
        unsigned long long acc2[8][4];
        #pragma unroll
        for (int i = 0; i < 8; i++)
            #pragma unroll
            for (int j = 0; j < 4; j++)
                acc2[i][j] = 0ull;

        // ---- preload k-tile 0 ----
        {
            #pragma unroll
            for (int l = 0; l < 2; l++) {
                int f = tid + l * 256;
                int r = f >> 2, kq = f & 3;
                float4 va = *(const float4*)(ftr + (size_t)(row0 + r) * DD + kq * 4);
                float4 vb = *(const float4*)(ftr + (size_t)(col0 + r) * DD + kq * 4);
                As[0][kq * 4 + 0][r] = va.x; As[0][kq * 4 + 1][r] = va.y;
                As[0][kq * 4 + 2][r] = va.z; As[0][kq * 4 + 3][r] = va.w;
                Bs[0][kq * 4 + 0][r] = vb.x; Bs[0][kq * 4 + 1][r] = vb.y;
                Bs[0][kq * 4 + 2][r] = vb.z; Bs[0][kq * 4 + 3][r] = vb.w;
            }
        }
        __syncthreads();

        // ---- main loop over k-tiles, double buffered ----
        for (int kt = 0; kt < NT; kt++) {
            const int cur = kt & 1;
            float4 va[2], vb[2];
            const bool more = (kt + 1) < NT;

            if (more) {
                const int k0 = (kt + 1) * BK;
                #pragma unroll
                for (int l = 0; l < 2; l++) {
                    int f = tid + l * 256;
                    int r = f >> 2, kq = f & 3;
                    va[l] = *(const float4*)(ftr + (size_t)(row0 + r) * DD + k0 + kq * 4);
                    vb[l] = *(const float4*)(ftr + (size_t)(col0 + r) * DD + k0 + kq * 4);
                }
            }

            #pragma unroll
            for (int k = 0; k < BK; k++) {
                float a[8];
                *(float4*)&a[0] = *(const float4*)&As[cur][k][ty * 8 + 0];
                *(float4*)&a[4] = *(const float4*)&As[cur][k][ty * 8 + 4];
                // B pairs arrive pre-packed: 2x 128-bit loads = 4 f32x2 operands
                ulonglong2 b01 = *(const ulonglong2*)&Bs[cur][k][tx * 8 + 0];
                ulonglong2 b23 = *(const ulonglong2*)&Bs[cur][k][tx * 8 + 4];
                unsigned long long b2[4] = {b01.x, b01.y, b23.x, b23.y};
                #pragma unroll
                for (int i = 0; i < 8; i++) {
                    unsigned long long ad;
                    DUP2(ad, a[i]);
                    FMA2(acc2[i][0], ad, b2[0]);
                    FMA2(acc2[i][1], ad, b2[1]);
                    FMA2(acc2[i][2], ad, b2[2]);
                    FMA2(acc2[i][3], ad, b2[3]);
                }
            }

            if (more) {
                const int nb = cur ^ 1;
                #pragma unroll
                for (int l = 0; l < 2; l++) {
                    int f = tid + l * 256;
                    int r = f >> 2, kq = f & 3;
                    As[nb][kq * 4 + 0][r] = va[l].x; As[nb][kq * 4 + 1][r] = va[l].y;
                    As[nb][kq * 4 + 2][r] = va[l].z; As[nb][kq * 4 + 3][r] = va[l].w;
                    Bs[nb][kq * 4 + 0][r] = vb[l].x; Bs[nb][kq * 4 + 1][r] = vb[l].y;
                    Bs[nb][kq * 4 + 2][r] = vb[l].z; Bs[nb][kq * 4 + 3][r] = vb[l].w;
                }
            }
            __syncthreads();
        }

        // unpack accumulators
        float acc[8][8];
        #pragma unroll
        for (int i = 0; i < 8; i++)
            #pragma unroll
            for (int j = 0; j < 4; j++)
                UNPK2(acc[i][2 * j], acc[i][2 * j + 1], acc2[i][j]);

        // ---- epilogue: row-direction masked argmin ----
        #pragma unroll
        for (int i = 0; i < 8; i++) {
            const int gi  = ty * 8 + i;
            const int lab = slabR[gi];
            unsigned long long best = 0xFFFFFFFFFFFFFFFFull;
            #pragma unroll
            for (int j = 0; j < 8; j++) {
                const int gj = col0 + tx * 8 + j;
                if (gj != lab) {
                    unsigned long long p =
                        ((unsigned long long)fkey(acc[i][j]) << 32) | (unsigned int)gj;
                    best = (p < best) ? p : best;
                }
            }
            atomicMin(&rowMin[gi], best);
        }

        // ---- epilogue: col-direction (transposed) masked argmin ----
        if (offdiag) {
            #pragma unroll
            for (int j = 0; j < 8; j++) {
                const int gj  = tx * 8 + j;
                const int lab = slabC[gj];
                unsigned long long best = 0xFFFFFFFFFFFFFFFFull;
                #pragma unroll
                for (int i = 0; i < 8; i++) {
                    const int gi = row0 + ty * 8 + i;
                    if (gi != lab) {
                        unsigned long long p =
                            ((unsigned long long)fkey(acc[i][j]) << 32) | (unsigned int)gi;
                        best = (p < best) ? p : best;
                    }
                }
                atomicMin(&colMin[gj], best);
            }
        }
        __syncthreads();

        if (tid < BM) {
            atomicMin(&g_min[row0 + tid], rowMin[tid]);
            if (offdiag) atomicMin(&g_min[col0 + tid], colMin[tid]);
        }
        __syncthreads();
    }
}

// ---------------------------------------------------------------------------
// Per-row loss: one warp per row (exact fp32).
// ---------------------------------------------------------------------------
__global__ __launch_bounds__(256)
void loss_kernel(const float* __restrict__ ftr,
                 const float* __restrict__ prototypes) {
    const int warp = (blockIdx.x * blockDim.x + threadIdx.x) >> 5;
    const int lane = threadIdx.x & 31;
    if (warp >= BSZ) return;
    const int r   = warp;
    const int lab = g_label[r];
    const int ni  = (int)(g_min[r] & 0xFFFFFFFFull);

    const float* xp = ftr + (size_t)r * DD;
    const float* yp = prototypes + (size_t)lab * DD;
    const float* np = ftr + (size_t)ni * DD;

    float pd = 0.0f, nd = 0.0f;
    #pragma unroll
    for (int t = 0; t < DD / 32; t++) {
        const int c = lane + t * 32;
        const float xv = xp[c];
        const float dy = xv - yp[c];
        const float dn = xv - np[c];
        pd = fmaf(dy, dy, pd);
        nd = fmaf(dn, dn, nd);
    }
    #pragma unroll
    for (int o = 16; o > 0; o >>= 1) {
        pd += __shfl_down_sync(0xFFFFFFFFu, pd, o);
        nd += __shfl_down_sync(0xFFFFFFFFu, nd, o);
    }
    if (lane == 0) g_loss[r] = fmaxf(pd - nd + MARGIN, 0.0f);
}

// ---------------------------------------------------------------------------
// Deterministic mean reduction (shuffle tree).
// ---------------------------------------------------------------------------
__global__ void reduce_kernel(float* __restrict__ out) {
    __shared__ float s[32];
    const int t = threadIdx.x;   // 1024
    float v = g_loss[t] + g_loss[t + 1024] + g_loss[t + 2048] + g_loss[t + 3072];
    #pragma unroll
    for (int o = 16; o > 0; o >>= 1) v += __shfl_down_sync(0xFFFFFFFFu, v, o);
    if ((t & 31) == 0) s[t >> 5] = v;
    __syncthreads();
    if (t < 32) {
        float w = s[t];
        #pragma unroll
        for (int o = 16; o > 0; o >>= 1) w += __shfl_down_sync(0xFFFFFFFFu, w, o);
        if (t == 0) out[0] = w / (float)BSZ;
    }
}

extern "C" void kernel_launch(void* const* d_in, const int* in_sizes, int n_in,
                              void* d_out, int out_size) {
    const float* ftr        = (const float*)d_in[0];
    // d_in[1] = teachor_ftr : unused by the reference computation
    const float* prototypes = (const float*)d_in[2];
    const int*   label_raw  = (const int*)d_in[3];   // int32 or int64 — sniffed on device
    float*       out        = (float*)d_out;

    prologue_kernel<<<BSZ / 256, 256>>>(label_raw);

    sim_argmin_kernel<<<GRID_SIM, 256>>>(ftr);   // persistent work-stealing over 528 tiles

    loss_kernel<<<(BSZ * 32) / 256, 256>>>(ftr, prototypes);

    reduce_kernel<<<1, 1024>>>(out);
}